// round 13
// baseline (speedup 1.0000x reference)
#include <cuda_runtime.h>
#include <cstdint>

// dim=4096, MAX_DIM=32, N_COMP=10000.
// gather_idx/gather_sign: [32,32,32] row-major (k,i,j), int32/float32.
// Output: ricci[4096*4096] row-major + scalar trace at index 4096*4096.

#define DIMN 4096
#define MD   32
#define TPB  256

// 64KB chunks (4 rows each).
//   blocks 0..7    : patch blocks, 4 rows each (rows 0..31) -> 1 x 64KB store
//   blocks 8..261  : fill blocks, 4 x 64KB = 256KB each (rows 32..4095)
//                    254 * 4 = 1016 chunks = 63.5MB exactly.
#define PATCH_BLKS 8
#define FILL_BLKS  254
#define GRID       (PATCH_BLKS + FILL_BLKS)      // 262
#define SBUF_FLOATS 16384                         // 64KB
#define SBUF_BYTES  (SBUF_FLOATS * 4)
#define FILL_STORES 4

__device__ __forceinline__ void bulk_store(float* gdst, uint32_t ssrc, uint32_t bytes)
{
    asm volatile(
        "cp.async.bulk.global.shared::cta.bulk_group [%0], [%1], %2;"
        :: "l"(gdst), "r"(ssrc), "r"(bytes) : "memory");
}

__global__ __launch_bounds__(TPB)
void ricci_tma4_kernel(const float* __restrict__ comp,
                       const int*   __restrict__ gidx,
                       const float* __restrict__ gsgn,
                       float* __restrict__ out)
{
    extern __shared__ __align__(128) float sbuf[];       // 64KB dynamic

    const int b = blockIdx.x;
    const int t = threadIdx.x;

    // Zero the SMEM buffer (16 float4 per thread).
    float4* s4 = reinterpret_cast<float4*>(sbuf);
    #pragma unroll
    for (int n = t; n < SBUF_FLOATS / 4; n += TPB)
        s4[n] = make_float4(0.f, 0.f, 0.f, 0.f);

    const uint32_t sbase = (uint32_t)__cvta_generic_to_shared(sbuf);

    if (b >= PATCH_BLKS) {
        // Fill block: 4 x 64KB bulk stores, one per warp (warps 0..3),
        // independent bulk groups to keep multiple ops in flight.
        __syncthreads();
        if ((t & 31) == 0 && t < 128) {
            const int w = t >> 5;                 // 0..3
            asm volatile("fence.proxy.async.shared::cta;" ::: "memory");
            float* gdst = out + (size_t)MD * DIMN
                        + ((size_t)(b - PATCH_BLKS) * FILL_STORES + w) * SBUF_FLOATS;
            bulk_store(gdst, sbase, SBUF_BYTES);
            asm volatile("cp.async.bulk.commit_group;" ::: "memory");
            // Wait only for the SMEM source read; write visibility is
            // guaranteed at the kernel boundary.
            asm volatile("cp.async.bulk.wait_group.read 0;" ::: "memory");
        }
        __syncthreads();
        return;
    }

    // Patch block: rows 4b..4b+3. Threads 0..127 compute one element each.
    if (t < 128) {
        const int i = 4 * b + (t >> 5);
        const int j = t & 31;
        float r = 0.f;
        #pragma unroll
        for (int k = 0; k < MD; k++) {
            const int o = k * (MD * MD) + i * MD + j;
            r += gsgn[o] * comp[gidx[o]];
        }
        sbuf[(t >> 5) * DIMN + j] = r;
    }

    // Block 0, warp 5 (threads 160..191): trace scalar via shuffle reduce
    // (fixed order -> deterministic). Scalar lies outside the bulk region.
    if (b == 0 && t >= 160 && t < 192) {
        const int d = t - 160;
        float s = 0.f;
        #pragma unroll
        for (int k = 0; k < MD; k++) {
            const int o = k * (MD * MD) + d * MD + d;
            s += gsgn[o] * comp[gidx[o]];
        }
        #pragma unroll
        for (int off = 16; off > 0; off >>= 1)
            s += __shfl_down_sync(0xFFFFFFFFu, s, off);
        if (d == 0) out[(size_t)DIMN * DIMN] = s;
    }

    __syncthreads();
    if (t == 0) {
        asm volatile("fence.proxy.async.shared::cta;" ::: "memory");
        bulk_store(out + (size_t)b * SBUF_FLOATS, sbase, SBUF_BYTES);
        asm volatile("cp.async.bulk.commit_group;" ::: "memory");
        asm volatile("cp.async.bulk.wait_group.read 0;" ::: "memory");
    }
    __syncthreads();
}

extern "C" void kernel_launch(void* const* d_in, const int* in_sizes, int n_in,
                              void* d_out, int out_size)
{
    const float* comp = (const float*)d_in[0];   // components [10000] f32
    const int*   gidx = (const int*)  d_in[1];   // gather_idx [32,32,32] i32
    const float* gsgn = (const float*)d_in[2];   // gather_sign [32,32,32] f32

    float* out = (float*)d_out;

    // Idempotent attribute set (host-side, no allocation, deterministic).
    cudaFuncSetAttribute(ricci_tma4_kernel,
                         cudaFuncAttributeMaxDynamicSharedMemorySize,
                         SBUF_BYTES);

    ricci_tma4_kernel<<<GRID, TPB, SBUF_BYTES>>>(comp, gidx, gsgn, out);
}